// round 15
// baseline (speedup 1.0000x reference)
#include <cuda_runtime.h>
#include <cstdint>

#define NVOX 400000
#define NPTS 800000

// ---------------- scratch (device globals; zero-initialized at load) -------
__device__ float g_rW1 [(size_t)NVOX * 64];        // red @ W_lin1[0:64]  102.4 MB
__device__ float g_s32 [(size_t)4 * NVOX * 32];    // seg sums of red@Watt 204.8 MB
__device__ float g_cnt [(size_t)4 * NVOX];         // 6.4 MB
__device__ float g_proj[(size_t)NVOX * 64];        // 102.4 MB
__device__ int   g_vout[(size_t)NVOX];             // voxel -> out-row+1 (0 = absent)

// tf32 weights in B-fragment PAIR-INTERLEAVED layout:
//   pair(kt,nt,tg,g) = { W[kt*8+tg][nt*8+g], W[kt*8+tg+4][nt*8+g] }
//   index = ((kt*NT + nt)*4 + tg)*8 + g      (NT = N/8)
__device__ uint2 g_pWred[2048];        // 64x64, NT=8
__device__ uint2 g_pW1  [2048];        // 64x64, NT=8
__device__ uint2 g_pWatt[4 * 1024];    // 4 x 64x32, NT=4
__device__ uint2 g_pWfc [512];         // 32x32, NT=4
__device__ uint2 g_pWfcs[4 * 512];     // 4 x 32x32, NT=4
__device__ uint2 g_pWc  [1024];        // 32x64 (Wout @ W1[64:]), NT=8
__device__ uint2 g_pW2  [2048];        // 64x64, NT=8

__device__ __forceinline__ float sigm(float x) { return 1.f / (1.f + __expf(-x)); }

__device__ __forceinline__ void amaxf(float* a, float v) {
    if (v >= 0.f) atomicMax((int*)a, __float_as_int(v));
    else          atomicMin((unsigned int*)a, __float_as_uint(v));
}

__device__ __forceinline__ void red2(float* p, float a, float b) {
    asm volatile("red.global.add.v2.f32 [%0], {%1,%2};"
                 :: "l"(p), "f"(a), "f"(b) : "memory");
}

__device__ __forceinline__ unsigned tf32cvt(float f) {
    unsigned u; asm("cvt.rna.tf32.f32 %0, %1;" : "=r"(u) : "f"(f)); return u;
}

__device__ __forceinline__ void mma_tf32(
    float& d0, float& d1, float& d2, float& d3,
    unsigned a0, unsigned a1, unsigned a2, unsigned a3,
    unsigned b0, unsigned b1)
{
    asm volatile(
        "mma.sync.aligned.m16n8k8.row.col.f32.tf32.tf32.f32 "
        "{%0,%1,%2,%3}, {%4,%5,%6,%7}, {%8,%9}, {%0,%1,%2,%3};"
        : "+f"(d0), "+f"(d1), "+f"(d2), "+f"(d3)
        : "r"(a0), "r"(a1), "r"(a2), "r"(a3), "r"(b0), "r"(b1));
}

// ---------------- init kernels ---------------------------------------------
__global__ void k_fill_out(float* __restrict__ out, int n) {
    int i = blockIdx.x * blockDim.x + threadIdx.x;
    if (i < n) ((unsigned int*)out)[i] = 0xFF800000u;   // -inf
}

// Convert every weight matrix into pair-interleaved tf32 layout.
__global__ void k_cvt(const float* __restrict__ Wred, const float* __restrict__ W1,
                      const float* __restrict__ Watt, const float* __restrict__ Wfc,
                      const float* __restrict__ Wfcs, const float* __restrict__ W2,
                      const float* __restrict__ Wout)
{
    int p = blockIdx.x * 256 + threadIdx.x;   // 0..2047
    int g  = p & 7;
    int tg = (p >> 3) & 3;

    {
        int nt = (p >> 5) & 7, kt = p >> 8;
        int k0 = kt * 8 + tg, k1 = k0 + 4, n = nt * 8 + g;
        g_pWred[p] = make_uint2(tf32cvt(__ldg(Wred + k0 * 64 + n)),
                                tf32cvt(__ldg(Wred + k1 * 64 + n)));
        g_pW1[p]   = make_uint2(tf32cvt(__ldg(W1 + k0 * 64 + n)),
                                tf32cvt(__ldg(W1 + k1 * 64 + n)));
        g_pW2[p]   = make_uint2(tf32cvt(__ldg(W2 + k0 * 64 + n)),
                                tf32cvt(__ldg(W2 + k1 * 64 + n)));
    }
    {
        int j = p >> 10;
        int q = p & 1023;
        int nt = (q >> 5) & 3, kt = q >> 7;
        int k0 = kt * 8 + tg, k1 = k0 + 4, n = nt * 8 + g;
#pragma unroll
        for (int jj = 0; jj < 2; jj++) {
            int jm = j * 2 + jj;
            g_pWatt[jm * 1024 + q] =
                make_uint2(tf32cvt(__ldg(Watt + (size_t)jm * 2048 + k0 * 32 + n)),
                           tf32cvt(__ldg(Watt + (size_t)jm * 2048 + k1 * 32 + n)));
        }
    }
    if (p < 512) {
        int nt = (p >> 5) & 3, kt = p >> 7;
        int k0 = kt * 8 + tg, k1 = k0 + 4, n = nt * 8 + g;
        g_pWfc[p] = make_uint2(tf32cvt(__ldg(Wfc + k0 * 32 + n)),
                               tf32cvt(__ldg(Wfc + k1 * 32 + n)));
    }
    {
        int j = p >> 9;
        int q = p & 511;
        int nt = (q >> 5) & 3, kt = q >> 7;
        int k0 = kt * 8 + tg, k1 = k0 + 4, n = nt * 8 + g;
        g_pWfcs[j * 512 + q] =
            make_uint2(tf32cvt(__ldg(Wfcs + (size_t)j * 1024 + k0 * 32 + n)),
                       tf32cvt(__ldg(Wfcs + (size_t)j * 1024 + k1 * 32 + n)));
    }
    if (p < 1024) {
        int nt = (p >> 5) & 7, kt = p >> 8;
        int k0 = kt * 8 + tg, k1 = k0 + 4, n = nt * 8 + g;
        float s0 = 0.f, s1 = 0.f;
        for (int t = 0; t < 64; t++) {
            float w1v = __ldg(W1 + (64 + t) * 64 + n);
            s0 += __ldg(Wout + k0 * 64 + t) * w1v;
            s1 += __ldg(Wout + k1 * 64 + t) * w1v;
        }
        g_pWc[p] = make_uint2(tf32cvt(s0), tf32cvt(s1));
    }
}

// ---------------- K1: tf32 MMA: red; rW1; scatter t_j from D-frags ---------
__global__ __launch_bounds__(128) void k_redmma(
    const float* __restrict__ x, const float* __restrict__ b,
    const int* __restrict__ i0, const int* __restrict__ i1,
    const int* __restrict__ i2, const int* __restrict__ i3)
{
    __shared__ float stage[4][1088];

    int tid = threadIdx.x;
    int warp = tid >> 5, lane = tid & 31;
    int g  = lane >> 2;
    int tg = lane & 3;
    int vbase = (blockIdx.x * 4 + warp) * 16;
    float* st = stage[warp];     // [16][68]

    {
        const float4* xsrc = (const float4*)(x + (size_t)vbase * 64);
#pragma unroll
        for (int i = 0; i < 8; i++) {
            int idx = lane + i * 32;
            int row = idx >> 4, c4 = idx & 15;
            *(float4*)(st + row * 68 + c4 * 4) = __ldg(xsrc + idx);
        }
    }
    __syncwarp();

    unsigned a[8][4];
#pragma unroll
    for (int kt = 0; kt < 8; kt++) {
        a[kt][0] = tf32cvt(st[g * 68       + kt * 8 + tg]);
        a[kt][1] = tf32cvt(st[(g + 8) * 68 + kt * 8 + tg]);
        a[kt][2] = tf32cvt(st[g * 68       + kt * 8 + tg + 4]);
        a[kt][3] = tf32cvt(st[(g + 8) * 68 + kt * 8 + tg + 4]);
    }
    __syncwarp();

    // red = relu(x @ Wred + b) -> stage
#pragma unroll
    for (int nt = 0; nt < 8; nt++) {
        float2 bb2 = __ldg((const float2*)(b + nt * 8 + 2 * tg));
        float d0 = bb2.x, d1 = bb2.y, d2 = bb2.x, d3 = bb2.y;
#pragma unroll
        for (int kt = 0; kt < 8; kt++) {
            uint2 bb = __ldg(g_pWred + ((kt * 8 + nt) * 4 + tg) * 8 + g);
            mma_tf32(d0, d1, d2, d3, a[kt][0], a[kt][1], a[kt][2], a[kt][3], bb.x, bb.y);
        }
        *(float2*)(st + g * 68       + nt * 8 + 2 * tg) =
            make_float2(fmaxf(d0, 0.f), fmaxf(d1, 0.f));
        *(float2*)(st + (g + 8) * 68 + nt * 8 + 2 * tg) =
            make_float2(fmaxf(d2, 0.f), fmaxf(d3, 0.f));
    }
    __syncwarp();

#pragma unroll
    for (int kt = 0; kt < 8; kt++) {
        a[kt][0] = tf32cvt(st[g * 68       + kt * 8 + tg]);
        a[kt][1] = tf32cvt(st[(g + 8) * 68 + kt * 8 + tg]);
        a[kt][2] = tf32cvt(st[g * 68       + kt * 8 + tg + 4]);
        a[kt][3] = tf32cvt(st[(g + 8) * 68 + kt * 8 + tg + 4]);
    }

    // rW1 = red @ W1[0:64] -> global
    float* rbase = g_rW1 + (size_t)vbase * 64;
#pragma unroll
    for (int nt = 0; nt < 8; nt++) {
        float d0 = 0.f, d1 = 0.f, d2 = 0.f, d3 = 0.f;
#pragma unroll
        for (int kt = 0; kt < 8; kt++) {
            uint2 bb = __ldg(g_pW1 + ((kt * 8 + nt) * 4 + tg) * 8 + g);
            mma_tf32(d0, d1, d2, d3, a[kt][0], a[kt][1], a[kt][2], a[kt][3], bb.x, bb.y);
        }
        *(float2*)(rbase + (size_t)g * 64       + nt * 8 + 2 * tg) = make_float2(d0, d1);
        *(float2*)(rbase + (size_t)(g + 8) * 64 + nt * 8 + 2 * tg) = make_float2(d2, d3);
    }

    // t_j = red @ Watt[j]: scatter straight from D-fragments
    const int* invs[4] = {i0, i1, i2, i3};
#pragma unroll
    for (int j = 0; j < 4; j++) {
        int s_lo = __ldg(invs[j] + vbase + g);
        int s_hi = __ldg(invs[j] + vbase + g + 8);
        float* base_lo = g_s32 + ((size_t)j * NVOX + s_lo) * 32;
        float* base_hi = g_s32 + ((size_t)j * NVOX + s_hi) * 32;
#pragma unroll
        for (int nt = 0; nt < 4; nt++) {
            float d0 = 0.f, d1 = 0.f, d2 = 0.f, d3 = 0.f;
#pragma unroll
            for (int kt = 0; kt < 8; kt++) {
                uint2 bb = __ldg(g_pWatt + j * 1024 + ((kt * 4 + nt) * 4 + tg) * 8 + g);
                mma_tf32(d0, d1, d2, d3, a[kt][0], a[kt][1], a[kt][2], a[kt][3], bb.x, bb.y);
            }
            int col = nt * 8 + 2 * tg;
            red2(base_lo + col, d0, d1);
            red2(base_hi + col, d2, d3);
        }
        if (tg == 0) {
            atomicAdd(g_cnt + (size_t)j * NVOX + s_lo, 1.0f);
            atomicAdd(g_cnt + (size_t)j * NVOX + s_hi, 1.0f);
        }
    }
}

// ---------------- K3: fused gather(+att on the fly)+attention+MLP ----------
// att row computed inline: relu(s32[row]/cnt[row] + batt[j])  (cnt>=1 since
// the gathering voxel itself contributed to its segment).
#define FUSE3_SMEM_BYTES (11520 * 4)
__global__ __launch_bounds__(128, 4) void k_fuse3(
    const float* __restrict__ batt, const float* __restrict__ bfcs,
    const float* __restrict__ b2,
    const int* __restrict__ i0, const int* __restrict__ i1,
    const int* __restrict__ i2, const int* __restrict__ i3)
{
    extern __shared__ float fsm[];
    float* sSall  = fsm;            // 4 warps x 2304
    float* wrkall = fsm + 9216;     // 4 warps x 576

    int tid = threadIdx.x;
    int warp = tid >> 5, lane = tid & 31;
    int g  = lane >> 2;
    int tg = lane & 3;
    int vbase = (blockIdx.x * 4 + warp) * 16;
    float* sS  = sSall  + warp * 2304;   // [4][16][36]
    float* wrk = wrkall + warp * 576;    // [16][36]

    // 1) gather att rows from s32/cnt: 64 rows, 2 per lane
#pragma unroll
    for (int rep = 0; rep < 2; rep++) {
        int rid = rep * 32 + lane;
        int vox = rid >> 2, j = rid & 3;
        const int* ip = (j == 0) ? i0 : (j == 1) ? i1 : (j == 2) ? i2 : i3;
        int s = __ldg(ip + vbase + vox);
        size_t row = (size_t)j * NVOX + s;
        float ic = 1.f / g_cnt[row];
        const float4* src = (const float4*)(g_s32 + row * 32);
        float* dst = sS + j * 576 + vox * 36;
#pragma unroll
        for (int q = 0; q < 8; q++) {
            float4 v = __ldg(src + q);
            float4 o;
            o.x = fmaxf(v.x * ic + __ldg(batt + j * 32 + 4 * q + 0), 0.f);
            o.y = fmaxf(v.y * ic + __ldg(batt + j * 32 + 4 * q + 1), 0.f);
            o.z = fmaxf(v.z * ic + __ldg(batt + j * 32 + 4 * q + 2), 0.f);
            o.w = fmaxf(v.w * ic + __ldg(batt + j * 32 + 4 * q + 3), 0.f);
            ((float4*)dst)[q] = o;
        }
    }
    __syncwarp();

    // 2) fS = sum_j s_j -> wrk [16][36]
#pragma unroll
    for (int i = 0; i < 16; i++) {
        float v = sS[i * 36 + lane] + sS[576 + i * 36 + lane]
                + sS[1152 + i * 36 + lane] + sS[1728 + i * 36 + lane];
        wrk[i * 36 + lane] = v;
    }
    __syncwarp();

    unsigned af[4][4];
#pragma unroll
    for (int kt = 0; kt < 4; kt++) {
        af[kt][0] = tf32cvt(wrk[g * 36       + kt * 8 + tg]);
        af[kt][1] = tf32cvt(wrk[(g + 8) * 36 + kt * 8 + tg]);
        af[kt][2] = tf32cvt(wrk[g * 36       + kt * 8 + tg + 4]);
        af[kt][3] = tf32cvt(wrk[(g + 8) * 36 + kt * 8 + tg + 4]);
    }
    __syncwarp();

    // 3) fZ = relu(fS @ Wfc) -> wrk
#pragma unroll
    for (int nt = 0; nt < 4; nt++) {
        float d0 = 0.f, d1 = 0.f, d2 = 0.f, d3 = 0.f;
#pragma unroll
        for (int kt = 0; kt < 4; kt++) {
            uint2 bb = __ldg(g_pWfc + ((kt * 4 + nt) * 4 + tg) * 8 + g);
            mma_tf32(d0, d1, d2, d3, af[kt][0], af[kt][1], af[kt][2], af[kt][3], bb.x, bb.y);
        }
        *(float2*)(wrk + g * 36       + nt * 8 + 2 * tg) =
            make_float2(fmaxf(d0, 0.f), fmaxf(d1, 0.f));
        *(float2*)(wrk + (g + 8) * 36 + nt * 8 + 2 * tg) =
            make_float2(fmaxf(d2, 0.f), fmaxf(d3, 0.f));
    }
    __syncwarp();

    unsigned az[4][4];
#pragma unroll
    for (int kt = 0; kt < 4; kt++) {
        az[kt][0] = tf32cvt(wrk[g * 36       + kt * 8 + tg]);
        az[kt][1] = tf32cvt(wrk[(g + 8) * 36 + kt * 8 + tg]);
        az[kt][2] = tf32cvt(wrk[g * 36       + kt * 8 + tg + 4]);
        az[kt][3] = tf32cvt(wrk[(g + 8) * 36 + kt * 8 + tg + 4]);
    }
    __syncwarp();

    // 4) m = sum_j s_j * sigm(fZ @ Wfcs[j] + bfcs[j])
    float m0[4], m1[4], m2[4], m3[4];
#pragma unroll
    for (int nt = 0; nt < 4; nt++) { m0[nt] = 0.f; m1[nt] = 0.f; m2[nt] = 0.f; m3[nt] = 0.f; }
#pragma unroll
    for (int j = 0; j < 4; j++) {
#pragma unroll
        for (int nt = 0; nt < 4; nt++) {
            int col = nt * 8 + 2 * tg;
            float2 bb2 = __ldg((const float2*)(bfcs + j * 32 + col));
            float d0 = bb2.x, d1 = bb2.y, d2 = bb2.x, d3 = bb2.y;
#pragma unroll
            for (int kt = 0; kt < 4; kt++) {
                uint2 bb = __ldg(g_pWfcs + j * 512 + ((kt * 4 + nt) * 4 + tg) * 8 + g);
                mma_tf32(d0, d1, d2, d3, az[kt][0], az[kt][1], az[kt][2], az[kt][3], bb.x, bb.y);
            }
            float s0 = sS[j * 576 + g * 36 + col];
            float s1 = sS[j * 576 + g * 36 + col + 1];
            float s2 = sS[j * 576 + (g + 8) * 36 + col];
            float s3 = sS[j * 576 + (g + 8) * 36 + col + 1];
            m0[nt] += s0 * sigm(d0);
            m1[nt] += s1 * sigm(d1);
            m2[nt] += s2 * sigm(d2);
            m3[nt] += s3 * sigm(d3);
        }
    }
    __syncwarp();

    // 5) stage m -> wrk, read A-frags
#pragma unroll
    for (int nt = 0; nt < 4; nt++) {
        int col = nt * 8 + 2 * tg;
        *(float2*)(wrk + g * 36       + col) = make_float2(m0[nt], m1[nt]);
        *(float2*)(wrk + (g + 8) * 36 + col) = make_float2(m2[nt], m3[nt]);
    }
    __syncwarp();
    unsigned am[4][4];
#pragma unroll
    for (int kt = 0; kt < 4; kt++) {
        am[kt][0] = tf32cvt(wrk[g * 36       + kt * 8 + tg]);
        am[kt][1] = tf32cvt(wrk[(g + 8) * 36 + kt * 8 + tg]);
        am[kt][2] = tf32cvt(wrk[g * 36       + kt * 8 + tg + 4]);
        am[kt][3] = tf32cvt(wrk[(g + 8) * 36 + kt * 8 + tg + 4]);
    }
    __syncwarp();

    // 6) h = relu(rW1 + m @ Wc) -> hst (reuse sS region, stride 68)
    float* hst = sS;
    const float* rbase = g_rW1 + (size_t)vbase * 64;
#pragma unroll
    for (int nt = 0; nt < 8; nt++) {
        float2 c01 = *(const float2*)(rbase + (size_t)g * 64       + nt * 8 + 2 * tg);
        float2 c23 = *(const float2*)(rbase + (size_t)(g + 8) * 64 + nt * 8 + 2 * tg);
        float d0 = c01.x, d1 = c01.y, d2 = c23.x, d3 = c23.y;
#pragma unroll
        for (int kt = 0; kt < 4; kt++) {
            uint2 bb = __ldg(g_pWc + ((kt * 8 + nt) * 4 + tg) * 8 + g);
            mma_tf32(d0, d1, d2, d3, am[kt][0], am[kt][1], am[kt][2], am[kt][3], bb.x, bb.y);
        }
        *(float2*)(hst + g * 68       + nt * 8 + 2 * tg) =
            make_float2(fmaxf(d0, 0.f), fmaxf(d1, 0.f));
        *(float2*)(hst + (g + 8) * 68 + nt * 8 + 2 * tg) =
            make_float2(fmaxf(d2, 0.f), fmaxf(d3, 0.f));
    }
    __syncwarp();

    unsigned ah[8][4];
#pragma unroll
    for (int kt = 0; kt < 8; kt++) {
        ah[kt][0] = tf32cvt(hst[g * 68       + kt * 8 + tg]);
        ah[kt][1] = tf32cvt(hst[(g + 8) * 68 + kt * 8 + tg]);
        ah[kt][2] = tf32cvt(hst[g * 68       + kt * 8 + tg + 4]);
        ah[kt][3] = tf32cvt(hst[(g + 8) * 68 + kt * 8 + tg + 4]);
    }

    // 7) proj = h @ W2 + b2 -> g_proj
    float* pbase = g_proj + (size_t)vbase * 64;
#pragma unroll
    for (int nt = 0; nt < 8; nt++) {
        float2 bb2 = __ldg((const float2*)(b2 + nt * 8 + 2 * tg));
        float d0 = bb2.x, d1 = bb2.y, d2 = bb2.x, d3 = bb2.y;
#pragma unroll
        for (int kt = 0; kt < 8; kt++) {
            uint2 bb = __ldg(g_pW2 + ((kt * 8 + nt) * 4 + tg) * 8 + g);
            mma_tf32(d0, d1, d2, d3, ah[kt][0], ah[kt][1], ah[kt][2], ah[kt][3], bb.x, bb.y);
        }
        *(float2*)(pbase + (size_t)g * 64       + nt * 8 + 2 * tg) = make_float2(d0, d1);
        *(float2*)(pbase + (size_t)(g + 8) * 64 + nt * 8 + 2 * tg) = make_float2(d2, d3);
    }
}

// ---------------- K3b: restore zero invariant in s32/cnt (after fuse3) -----
__global__ __launch_bounds__(256) void k_clean()
{
    long long t = (long long)blockIdx.x * 256 + threadIdx.x;   // 4*NVOX*8 threads
    long long row = t >> 3;
    int q = (int)(t & 7);
    bool live = false;
    float c = 0.f;
    if (row < (long long)4 * NVOX) {
        c = g_cnt[row];
        live = (c != 0.f);
    }
    if (live)
        ((float4*)(g_s32 + row * 32))[q] = make_float4(0.f, 0.f, 0.f, 0.f);
    __syncwarp();
    if (live && q == 0) g_cnt[row] = 0.f;
}

// ---------------- K4a: point -> voxel out-row map (idempotent) --------------
__global__ __launch_bounds__(256) void k_map(
    const int* __restrict__ invp, const int* __restrict__ invo)
{
    int p = blockIdx.x * 256 + threadIdx.x;
    if (p >= NPTS) return;
    g_vout[__ldg(invp + p)] = __ldg(invo + p) + 1;
}

// ---------------- K4b: per present voxel, segment-max proj into out --------
__global__ __launch_bounds__(256) void k_pmax(float* __restrict__ out)
{
    int t = blockIdx.x * 256 + threadIdx.x;
    int v = t >> 4, q = t & 15;
    if (v >= NVOX) return;
    int o = g_vout[v];
    if (o == 0) return;
    o--;
    float4 val = __ldg((const float4*)(g_proj + (size_t)v * 64) + q);
    float* ob = out + (size_t)o * 64 + q * 4;
    amaxf(ob + 0, val.x); amaxf(ob + 1, val.y);
    amaxf(ob + 2, val.z); amaxf(ob + 3, val.w);
}

// ---------------- launch ----------------------------------------------------
// Inputs identified by ELEMENT COUNT + first-appearance order (dict order):
//   400000 x4 -> inv0..inv3 ; 800000 x2 -> inv_pts, inv_out ; 25600000 -> x
//   4096 x3 -> W_red, W_fcs, W_lin2 ; 8192 x2 -> W_att, W_lin1
//   64 x2 -> b_red, b_lin2 ; 128 x2 -> b_att, b_fcs ; 1024 -> W_fc ; 2048 -> W_out
extern "C" void kernel_launch(void* const* d_in, const int* in_sizes, int n_in,
                              void* d_out, int out_size)
{
    const float *x = 0, *Wred = 0, *bred = 0, *Watt = 0, *batt = 0;
    const float *Wfcs = 0, *bfcs = 0, *Wfc = 0, *Wout = 0, *W1 = 0, *W2 = 0, *b2 = 0;
    const int *i0 = 0, *i1 = 0, *i2 = 0, *i3 = 0, *invp = 0, *invo = 0;

    int c400k = 0, c800k = 0, c4096 = 0, c8192 = 0, c64 = 0, c128 = 0;
    for (int i = 0; i < n_in; i++) {
        int s = in_sizes[i];
        const void* p = d_in[i];
        switch (s) {
            case 400000:
                if      (c400k == 0) i0 = (const int*)p;
                else if (c400k == 1) i1 = (const int*)p;
                else if (c400k == 2) i2 = (const int*)p;
                else                 i3 = (const int*)p;
                c400k++; break;
            case 800000:
                if (c800k == 0) invp = (const int*)p; else invo = (const int*)p;
                c800k++; break;
            case 25600000: x = (const float*)p; break;
            case 4096:
                if      (c4096 == 0) Wred = (const float*)p;
                else if (c4096 == 1) Wfcs = (const float*)p;
                else                 W2   = (const float*)p;
                c4096++; break;
            case 8192:
                if (c8192 == 0) Watt = (const float*)p; else W1 = (const float*)p;
                c8192++; break;
            case 64:
                if (c64 == 0) bred = (const float*)p; else b2 = (const float*)p;
                c64++; break;
            case 128:
                if (c128 == 0) batt = (const float*)p; else bfcs = (const float*)p;
                c128++; break;
            case 1024: Wfc  = (const float*)p; break;
            case 2048: Wout = (const float*)p; break;
            default: break;   // size-1 scalars ignored
        }
    }

    float* out = (float*)d_out;

    static int smem_set = 0;
    if (!smem_set) {
        cudaFuncSetAttribute(k_fuse3, cudaFuncAttributeMaxDynamicSharedMemorySize,
                             FUSE3_SMEM_BYTES);
        smem_set = 1;
    }

    // Launch order puts k_fuse3 at position 4 (ncu keyhole captures launch #4).
    k_cvt<<<8, 256>>>(Wred, W1, Watt, Wfc, Wfcs, W2, Wout);

    k_redmma<<<NVOX / 64, 128>>>(x, bred, i0, i1, i2, i3);

    k_fill_out<<<(out_size + 255) / 256, 256>>>(out, out_size);

    k_fuse3<<<NVOX / 64, 128, FUSE3_SMEM_BYTES>>>(batt, bfcs, b2, i0, i1, i2, i3);

    {
        long long tot = (long long)4 * NVOX * 8;
        k_clean<<<(unsigned)((tot + 255) / 256), 256>>>();
    }

    k_map<<<(NPTS + 255) / 256, 256>>>(invp, invo);

    k_pmax<<<((size_t)NVOX * 16 + 255) / 256, 256>>>(out);
}

// round 16
// speedup vs baseline: 1.1028x; 1.1028x over previous
#include <cuda_runtime.h>
#include <cstdint>

#define NVOX 400000
#define NPTS 800000

// ---------------- scratch (device globals; zero-initialized at load) -------
__device__ float g_rW1 [(size_t)NVOX * 64];        // red @ W_lin1[0:64]  102.4 MB
__device__ float g_s32 [(size_t)4 * NVOX * 32];    // seg sums of red@Watt 204.8 MB
__device__ float g_cnt [(size_t)4 * NVOX];         // 6.4 MB
__device__ float g_att [(size_t)4 * NVOX * 32];    // 204.8 MB
__device__ int   g_vout[(size_t)NVOX];             // voxel -> out-row+1 (0 = absent)

// tf32 weights in B-fragment PAIR-INTERLEAVED layout:
//   pair(kt,nt,tg,g) = { W[kt*8+tg][nt*8+g], W[kt*8+tg+4][nt*8+g] }
//   index = ((kt*NT + nt)*4 + tg)*8 + g      (NT = N/8)
__device__ uint2 g_pWred[2048];        // 64x64, NT=8
__device__ uint2 g_pW1  [2048];        // 64x64, NT=8
__device__ uint2 g_pWatt[4 * 1024];    // 4 x 64x32, NT=4
__device__ uint2 g_pWfc [512];         // 32x32, NT=4
__device__ uint2 g_pWfcs[4 * 512];     // 4 x 32x32, NT=4
__device__ uint2 g_pWc  [1024];        // 32x64 (Wout @ W1[64:]), NT=8
__device__ uint2 g_pW2  [2048];        // 64x64, NT=8

__device__ __forceinline__ float sigm(float x) { return 1.f / (1.f + __expf(-x)); }

__device__ __forceinline__ void amaxf(float* a, float v) {
    if (v >= 0.f) atomicMax((int*)a, __float_as_int(v));
    else          atomicMin((unsigned int*)a, __float_as_uint(v));
}

__device__ __forceinline__ void red2(float* p, float a, float b) {
    asm volatile("red.global.add.v2.f32 [%0], {%1,%2};"
                 :: "l"(p), "f"(a), "f"(b) : "memory");
}

__device__ __forceinline__ unsigned tf32cvt(float f) {
    unsigned u; asm("cvt.rna.tf32.f32 %0, %1;" : "=r"(u) : "f"(f)); return u;
}

__device__ __forceinline__ void mma_tf32(
    float& d0, float& d1, float& d2, float& d3,
    unsigned a0, unsigned a1, unsigned a2, unsigned a3,
    unsigned b0, unsigned b1)
{
    asm volatile(
        "mma.sync.aligned.m16n8k8.row.col.f32.tf32.tf32.f32 "
        "{%0,%1,%2,%3}, {%4,%5,%6,%7}, {%8,%9}, {%0,%1,%2,%3};"
        : "+f"(d0), "+f"(d1), "+f"(d2), "+f"(d3)
        : "r"(a0), "r"(a1), "r"(a2), "r"(a3), "r"(b0), "r"(b1));
}

// ---------------- init kernels ---------------------------------------------
__global__ void k_fill_out(float* __restrict__ out, int n) {
    int i = blockIdx.x * blockDim.x + threadIdx.x;
    if (i < n) ((unsigned int*)out)[i] = 0xFF800000u;   // -inf
}

// Convert every weight matrix into pair-interleaved tf32 layout.
__global__ void k_cvt(const float* __restrict__ Wred, const float* __restrict__ W1,
                      const float* __restrict__ Watt, const float* __restrict__ Wfc,
                      const float* __restrict__ Wfcs, const float* __restrict__ W2,
                      const float* __restrict__ Wout)
{
    int p = blockIdx.x * 256 + threadIdx.x;   // 0..2047
    int g  = p & 7;
    int tg = (p >> 3) & 3;

    {
        int nt = (p >> 5) & 7, kt = p >> 8;
        int k0 = kt * 8 + tg, k1 = k0 + 4, n = nt * 8 + g;
        g_pWred[p] = make_uint2(tf32cvt(__ldg(Wred + k0 * 64 + n)),
                                tf32cvt(__ldg(Wred + k1 * 64 + n)));
        g_pW1[p]   = make_uint2(tf32cvt(__ldg(W1 + k0 * 64 + n)),
                                tf32cvt(__ldg(W1 + k1 * 64 + n)));
        g_pW2[p]   = make_uint2(tf32cvt(__ldg(W2 + k0 * 64 + n)),
                                tf32cvt(__ldg(W2 + k1 * 64 + n)));
    }
    {
        int j = p >> 10;
        int q = p & 1023;
        int nt = (q >> 5) & 3, kt = q >> 7;
        int k0 = kt * 8 + tg, k1 = k0 + 4, n = nt * 8 + g;
#pragma unroll
        for (int jj = 0; jj < 2; jj++) {
            int jm = j * 2 + jj;
            g_pWatt[jm * 1024 + q] =
                make_uint2(tf32cvt(__ldg(Watt + (size_t)jm * 2048 + k0 * 32 + n)),
                           tf32cvt(__ldg(Watt + (size_t)jm * 2048 + k1 * 32 + n)));
        }
    }
    if (p < 512) {
        int nt = (p >> 5) & 3, kt = p >> 7;
        int k0 = kt * 8 + tg, k1 = k0 + 4, n = nt * 8 + g;
        g_pWfc[p] = make_uint2(tf32cvt(__ldg(Wfc + k0 * 32 + n)),
                               tf32cvt(__ldg(Wfc + k1 * 32 + n)));
    }
    {
        int j = p >> 9;
        int q = p & 511;
        int nt = (q >> 5) & 3, kt = q >> 7;
        int k0 = kt * 8 + tg, k1 = k0 + 4, n = nt * 8 + g;
        g_pWfcs[j * 512 + q] =
            make_uint2(tf32cvt(__ldg(Wfcs + (size_t)j * 1024 + k0 * 32 + n)),
                       tf32cvt(__ldg(Wfcs + (size_t)j * 1024 + k1 * 32 + n)));
    }
    if (p < 1024) {
        int nt = (p >> 5) & 7, kt = p >> 8;
        int k0 = kt * 8 + tg, k1 = k0 + 4, n = nt * 8 + g;
        float s0 = 0.f, s1 = 0.f;
        for (int t = 0; t < 64; t++) {
            float w1v = __ldg(W1 + (64 + t) * 64 + n);
            s0 += __ldg(Wout + k0 * 64 + t) * w1v;
            s1 += __ldg(Wout + k1 * 64 + t) * w1v;
        }
        g_pWc[p] = make_uint2(tf32cvt(s0), tf32cvt(s1));
    }
}

// ---------------- K1: tf32 MMA: red; rW1; scatter t_j from D-frags ---------
__global__ __launch_bounds__(128) void k_redmma(
    const float* __restrict__ x, const float* __restrict__ b,
    const int* __restrict__ i0, const int* __restrict__ i1,
    const int* __restrict__ i2, const int* __restrict__ i3)
{
    __shared__ float stage[4][1088];

    int tid = threadIdx.x;
    int warp = tid >> 5, lane = tid & 31;
    int g  = lane >> 2;
    int tg = lane & 3;
    int vbase = (blockIdx.x * 4 + warp) * 16;
    float* st = stage[warp];     // [16][68]

    {
        const float4* xsrc = (const float4*)(x + (size_t)vbase * 64);
#pragma unroll
        for (int i = 0; i < 8; i++) {
            int idx = lane + i * 32;
            int row = idx >> 4, c4 = idx & 15;
            *(float4*)(st + row * 68 + c4 * 4) = __ldg(xsrc + idx);
        }
    }
    __syncwarp();

    unsigned a[8][4];
#pragma unroll
    for (int kt = 0; kt < 8; kt++) {
        a[kt][0] = tf32cvt(st[g * 68       + kt * 8 + tg]);
        a[kt][1] = tf32cvt(st[(g + 8) * 68 + kt * 8 + tg]);
        a[kt][2] = tf32cvt(st[g * 68       + kt * 8 + tg + 4]);
        a[kt][3] = tf32cvt(st[(g + 8) * 68 + kt * 8 + tg + 4]);
    }
    __syncwarp();

    // red = relu(x @ Wred + b) -> stage
#pragma unroll
    for (int nt = 0; nt < 8; nt++) {
        float2 bb2 = __ldg((const float2*)(b + nt * 8 + 2 * tg));
        float d0 = bb2.x, d1 = bb2.y, d2 = bb2.x, d3 = bb2.y;
#pragma unroll
        for (int kt = 0; kt < 8; kt++) {
            uint2 bb = __ldg(g_pWred + ((kt * 8 + nt) * 4 + tg) * 8 + g);
            mma_tf32(d0, d1, d2, d3, a[kt][0], a[kt][1], a[kt][2], a[kt][3], bb.x, bb.y);
        }
        *(float2*)(st + g * 68       + nt * 8 + 2 * tg) =
            make_float2(fmaxf(d0, 0.f), fmaxf(d1, 0.f));
        *(float2*)(st + (g + 8) * 68 + nt * 8 + 2 * tg) =
            make_float2(fmaxf(d2, 0.f), fmaxf(d3, 0.f));
    }
    __syncwarp();

#pragma unroll
    for (int kt = 0; kt < 8; kt++) {
        a[kt][0] = tf32cvt(st[g * 68       + kt * 8 + tg]);
        a[kt][1] = tf32cvt(st[(g + 8) * 68 + kt * 8 + tg]);
        a[kt][2] = tf32cvt(st[g * 68       + kt * 8 + tg + 4]);
        a[kt][3] = tf32cvt(st[(g + 8) * 68 + kt * 8 + tg + 4]);
    }

    // rW1 = red @ W1[0:64] -> global
    float* rbase = g_rW1 + (size_t)vbase * 64;
#pragma unroll
    for (int nt = 0; nt < 8; nt++) {
        float d0 = 0.f, d1 = 0.f, d2 = 0.f, d3 = 0.f;
#pragma unroll
        for (int kt = 0; kt < 8; kt++) {
            uint2 bb = __ldg(g_pW1 + ((kt * 8 + nt) * 4 + tg) * 8 + g);
            mma_tf32(d0, d1, d2, d3, a[kt][0], a[kt][1], a[kt][2], a[kt][3], bb.x, bb.y);
        }
        *(float2*)(rbase + (size_t)g * 64       + nt * 8 + 2 * tg) = make_float2(d0, d1);
        *(float2*)(rbase + (size_t)(g + 8) * 64 + nt * 8 + 2 * tg) = make_float2(d2, d3);
    }

    // t_j = red @ Watt[j]: scatter straight from D-fragments
    const int* invs[4] = {i0, i1, i2, i3};
#pragma unroll
    for (int j = 0; j < 4; j++) {
        int s_lo = __ldg(invs[j] + vbase + g);
        int s_hi = __ldg(invs[j] + vbase + g + 8);
        float* base_lo = g_s32 + ((size_t)j * NVOX + s_lo) * 32;
        float* base_hi = g_s32 + ((size_t)j * NVOX + s_hi) * 32;
#pragma unroll
        for (int nt = 0; nt < 4; nt++) {
            float d0 = 0.f, d1 = 0.f, d2 = 0.f, d3 = 0.f;
#pragma unroll
            for (int kt = 0; kt < 8; kt++) {
                uint2 bb = __ldg(g_pWatt + j * 1024 + ((kt * 4 + nt) * 4 + tg) * 8 + g);
                mma_tf32(d0, d1, d2, d3, a[kt][0], a[kt][1], a[kt][2], a[kt][3], bb.x, bb.y);
            }
            int col = nt * 8 + 2 * tg;
            red2(base_lo + col, d0, d1);
            red2(base_hi + col, d2, d3);
        }
        if (tg == 0) {
            atomicAdd(g_cnt + (size_t)j * NVOX + s_lo, 1.0f);
            atomicAdd(g_cnt + (size_t)j * NVOX + s_hi, 1.0f);
        }
    }
}

// ---------------- K2: att = relu(s32/cnt + b); self-clean (8 thr/row) ------
__global__ __launch_bounds__(256) void k_scale(const float* __restrict__ batt)
{
    long long t = (long long)blockIdx.x * 256 + threadIdx.x;   // 4*NVOX*8 threads
    long long row = t >> 3;
    int q = (int)(t & 7);
    bool live = false;
    float c = 0.f;
    int j = 0;
    if (row < (long long)4 * NVOX) {
        j = (int)(row / NVOX);
        c = g_cnt[row];
        live = (c != 0.f);
    }
    if (live) {
        float invc = 1.f / c;
        float4* sp = (float4*)(g_s32 + row * 32) + q;
        float4* op = (float4*)(g_att + row * 32) + q;
        float4 v = *sp;
        float4 o;
        o.x = fmaxf(v.x * invc + __ldg(batt + j * 32 + 4 * q + 0), 0.f);
        o.y = fmaxf(v.y * invc + __ldg(batt + j * 32 + 4 * q + 1), 0.f);
        o.z = fmaxf(v.z * invc + __ldg(batt + j * 32 + 4 * q + 2), 0.f);
        o.w = fmaxf(v.w * invc + __ldg(batt + j * 32 + 4 * q + 3), 0.f);
        *op = o;
        *sp = make_float4(0.f, 0.f, 0.f, 0.f);      // restore zero for replay
    }
    __syncwarp();
    if (live && q == 0) g_cnt[row] = 0.f;
}

// ---------------- K3: fused gather+attention+MLP + segment-max epilogue ----
// 128 thr = 4 warps, 16 voxels/warp. smem: sS 4x[4*16][36] + wrk 4x[16][36].
// proj never hits memory: amaxf straight from D-fragments into out.
#define FUSE3_SMEM_BYTES (11520 * 4)
__global__ __launch_bounds__(128, 4) void k_fuse3(
    const float* __restrict__ bfcs, const float* __restrict__ b2,
    const int* __restrict__ i0, const int* __restrict__ i1,
    const int* __restrict__ i2, const int* __restrict__ i3,
    float* __restrict__ out)
{
    extern __shared__ float fsm[];
    float* sSall  = fsm;            // 4 warps x 2304
    float* wrkall = fsm + 9216;     // 4 warps x 576

    int tid = threadIdx.x;
    int warp = tid >> 5, lane = tid & 31;
    int g  = lane >> 2;
    int tg = lane & 3;
    int vbase = (blockIdx.x * 4 + warp) * 16;
    float* sS  = sSall  + warp * 2304;   // [4][16][36]
    float* wrk = wrkall + warp * 576;    // [16][36]

    // 1) gather att rows: 64 rows (16 vox x 4 scales), 2 rows per lane
#pragma unroll
    for (int rep = 0; rep < 2; rep++) {
        int rid = rep * 32 + lane;
        int vox = rid >> 2, j = rid & 3;
        const int* ip = (j == 0) ? i0 : (j == 1) ? i1 : (j == 2) ? i2 : i3;
        int s = __ldg(ip + vbase + vox);
        const float4* src = (const float4*)(g_att + ((size_t)j * NVOX + s) * 32);
        float* dst = sS + j * 576 + vox * 36;
#pragma unroll
        for (int q = 0; q < 8; q++)
            ((float4*)dst)[q] = __ldg(src + q);
    }
    __syncwarp();

    // 2) fS = sum_j s_j -> wrk [16][36]
#pragma unroll
    for (int i = 0; i < 16; i++) {
        float v = sS[i * 36 + lane] + sS[576 + i * 36 + lane]
                + sS[1152 + i * 36 + lane] + sS[1728 + i * 36 + lane];
        wrk[i * 36 + lane] = v;
    }
    __syncwarp();

    unsigned af[4][4];
#pragma unroll
    for (int kt = 0; kt < 4; kt++) {
        af[kt][0] = tf32cvt(wrk[g * 36       + kt * 8 + tg]);
        af[kt][1] = tf32cvt(wrk[(g + 8) * 36 + kt * 8 + tg]);
        af[kt][2] = tf32cvt(wrk[g * 36       + kt * 8 + tg + 4]);
        af[kt][3] = tf32cvt(wrk[(g + 8) * 36 + kt * 8 + tg + 4]);
    }
    __syncwarp();

    // 3) fZ = relu(fS @ Wfc) -> wrk
#pragma unroll
    for (int nt = 0; nt < 4; nt++) {
        float d0 = 0.f, d1 = 0.f, d2 = 0.f, d3 = 0.f;
#pragma unroll
        for (int kt = 0; kt < 4; kt++) {
            uint2 bb = __ldg(g_pWfc + ((kt * 4 + nt) * 4 + tg) * 8 + g);
            mma_tf32(d0, d1, d2, d3, af[kt][0], af[kt][1], af[kt][2], af[kt][3], bb.x, bb.y);
        }
        *(float2*)(wrk + g * 36       + nt * 8 + 2 * tg) =
            make_float2(fmaxf(d0, 0.f), fmaxf(d1, 0.f));
        *(float2*)(wrk + (g + 8) * 36 + nt * 8 + 2 * tg) =
            make_float2(fmaxf(d2, 0.f), fmaxf(d3, 0.f));
    }
    __syncwarp();

    unsigned az[4][4];
#pragma unroll
    for (int kt = 0; kt < 4; kt++) {
        az[kt][0] = tf32cvt(wrk[g * 36       + kt * 8 + tg]);
        az[kt][1] = tf32cvt(wrk[(g + 8) * 36 + kt * 8 + tg]);
        az[kt][2] = tf32cvt(wrk[g * 36       + kt * 8 + tg + 4]);
        az[kt][3] = tf32cvt(wrk[(g + 8) * 36 + kt * 8 + tg + 4]);
    }
    __syncwarp();

    // 4) m = sum_j s_j * sigm(fZ @ Wfcs[j] + bfcs[j])
    float m0[4], m1[4], m2[4], m3[4];
#pragma unroll
    for (int nt = 0; nt < 4; nt++) { m0[nt] = 0.f; m1[nt] = 0.f; m2[nt] = 0.f; m3[nt] = 0.f; }
#pragma unroll
    for (int j = 0; j < 4; j++) {
#pragma unroll
        for (int nt = 0; nt < 4; nt++) {
            int col = nt * 8 + 2 * tg;
            float2 bb2 = __ldg((const float2*)(bfcs + j * 32 + col));
            float d0 = bb2.x, d1 = bb2.y, d2 = bb2.x, d3 = bb2.y;
#pragma unroll
            for (int kt = 0; kt < 4; kt++) {
                uint2 bb = __ldg(g_pWfcs + j * 512 + ((kt * 4 + nt) * 4 + tg) * 8 + g);
                mma_tf32(d0, d1, d2, d3, az[kt][0], az[kt][1], az[kt][2], az[kt][3], bb.x, bb.y);
            }
            float s0 = sS[j * 576 + g * 36 + col];
            float s1 = sS[j * 576 + g * 36 + col + 1];
            float s2 = sS[j * 576 + (g + 8) * 36 + col];
            float s3 = sS[j * 576 + (g + 8) * 36 + col + 1];
            m0[nt] += s0 * sigm(d0);
            m1[nt] += s1 * sigm(d1);
            m2[nt] += s2 * sigm(d2);
            m3[nt] += s3 * sigm(d3);
        }
    }
    __syncwarp();

    // 5) stage m -> wrk, read A-frags
#pragma unroll
    for (int nt = 0; nt < 4; nt++) {
        int col = nt * 8 + 2 * tg;
        *(float2*)(wrk + g * 36       + col) = make_float2(m0[nt], m1[nt]);
        *(float2*)(wrk + (g + 8) * 36 + col) = make_float2(m2[nt], m3[nt]);
    }
    __syncwarp();
    unsigned am[4][4];
#pragma unroll
    for (int kt = 0; kt < 4; kt++) {
        am[kt][0] = tf32cvt(wrk[g * 36       + kt * 8 + tg]);
        am[kt][1] = tf32cvt(wrk[(g + 8) * 36 + kt * 8 + tg]);
        am[kt][2] = tf32cvt(wrk[g * 36       + kt * 8 + tg + 4]);
        am[kt][3] = tf32cvt(wrk[(g + 8) * 36 + kt * 8 + tg + 4]);
    }
    __syncwarp();

    // 6) h = relu(rW1 + m @ Wc) -> hst (reuse sS region, stride 68)
    float* hst = sS;
    const float* rbase = g_rW1 + (size_t)vbase * 64;
#pragma unroll
    for (int nt = 0; nt < 8; nt++) {
        float2 c01 = *(const float2*)(rbase + (size_t)g * 64       + nt * 8 + 2 * tg);
        float2 c23 = *(const float2*)(rbase + (size_t)(g + 8) * 64 + nt * 8 + 2 * tg);
        float d0 = c01.x, d1 = c01.y, d2 = c23.x, d3 = c23.y;
#pragma unroll
        for (int kt = 0; kt < 4; kt++) {
            uint2 bb = __ldg(g_pWc + ((kt * 8 + nt) * 4 + tg) * 8 + g);
            mma_tf32(d0, d1, d2, d3, am[kt][0], am[kt][1], am[kt][2], am[kt][3], bb.x, bb.y);
        }
        *(float2*)(hst + g * 68       + nt * 8 + 2 * tg) =
            make_float2(fmaxf(d0, 0.f), fmaxf(d1, 0.f));
        *(float2*)(hst + (g + 8) * 68 + nt * 8 + 2 * tg) =
            make_float2(fmaxf(d2, 0.f), fmaxf(d3, 0.f));
    }
    __syncwarp();

    unsigned ah[8][4];
#pragma unroll
    for (int kt = 0; kt < 8; kt++) {
        ah[kt][0] = tf32cvt(hst[g * 68       + kt * 8 + tg]);
        ah[kt][1] = tf32cvt(hst[(g + 8) * 68 + kt * 8 + tg]);
        ah[kt][2] = tf32cvt(hst[g * 68       + kt * 8 + tg + 4]);
        ah[kt][3] = tf32cvt(hst[(g + 8) * 68 + kt * 8 + tg + 4]);
    }

    // 7) proj = h @ W2 + b2 -> segment-max straight into out (no g_proj)
    int o_lo = __ldg(g_vout + vbase + g);
    int o_hi = __ldg(g_vout + vbase + g + 8);
    float* ob_lo = out + (size_t)(o_lo - 1) * 64;
    float* ob_hi = out + (size_t)(o_hi - 1) * 64;
#pragma unroll
    for (int nt = 0; nt < 8; nt++) {
        float2 bb2 = __ldg((const float2*)(b2 + nt * 8 + 2 * tg));
        float d0 = bb2.x, d1 = bb2.y, d2 = bb2.x, d3 = bb2.y;
#pragma unroll
        for (int kt = 0; kt < 8; kt++) {
            uint2 bb = __ldg(g_pW2 + ((kt * 8 + nt) * 4 + tg) * 8 + g);
            mma_tf32(d0, d1, d2, d3, ah[kt][0], ah[kt][1], ah[kt][2], ah[kt][3], bb.x, bb.y);
        }
        int col = nt * 8 + 2 * tg;
        if (o_lo) { amaxf(ob_lo + col, d0); amaxf(ob_lo + col + 1, d1); }
        if (o_hi) { amaxf(ob_hi + col, d2); amaxf(ob_hi + col + 1, d3); }
    }
}

// ---------------- K4a: point -> voxel out-row map (idempotent) --------------
__global__ __launch_bounds__(256) void k_map(
    const int* __restrict__ invp, const int* __restrict__ invo)
{
    int p = blockIdx.x * 256 + threadIdx.x;
    if (p >= NPTS) return;
    g_vout[__ldg(invp + p)] = __ldg(invo + p) + 1;
}

// ---------------- launch ----------------------------------------------------
// Inputs identified by ELEMENT COUNT + first-appearance order (dict order):
//   400000 x4 -> inv0..inv3 ; 800000 x2 -> inv_pts, inv_out ; 25600000 -> x
//   4096 x3 -> W_red, W_fcs, W_lin2 ; 8192 x2 -> W_att, W_lin1
//   64 x2 -> b_red, b_lin2 ; 128 x2 -> b_att, b_fcs ; 1024 -> W_fc ; 2048 -> W_out
extern "C" void kernel_launch(void* const* d_in, const int* in_sizes, int n_in,
                              void* d_out, int out_size)
{
    const float *x = 0, *Wred = 0, *bred = 0, *Watt = 0, *batt = 0;
    const float *Wfcs = 0, *bfcs = 0, *Wfc = 0, *Wout = 0, *W1 = 0, *W2 = 0, *b2 = 0;
    const int *i0 = 0, *i1 = 0, *i2 = 0, *i3 = 0, *invp = 0, *invo = 0;

    int c400k = 0, c800k = 0, c4096 = 0, c8192 = 0, c64 = 0, c128 = 0;
    for (int i = 0; i < n_in; i++) {
        int s = in_sizes[i];
        const void* p = d_in[i];
        switch (s) {
            case 400000:
                if      (c400k == 0) i0 = (const int*)p;
                else if (c400k == 1) i1 = (const int*)p;
                else if (c400k == 2) i2 = (const int*)p;
                else                 i3 = (const int*)p;
                c400k++; break;
            case 800000:
                if (c800k == 0) invp = (const int*)p; else invo = (const int*)p;
                c800k++; break;
            case 25600000: x = (const float*)p; break;
            case 4096:
                if      (c4096 == 0) Wred = (const float*)p;
                else if (c4096 == 1) Wfcs = (const float*)p;
                else                 W2   = (const float*)p;
                c4096++; break;
            case 8192:
                if (c8192 == 0) Watt = (const float*)p; else W1 = (const float*)p;
                c8192++; break;
            case 64:
                if (c64 == 0) bred = (const float*)p; else b2 = (const float*)p;
                c64++; break;
            case 128:
                if (c128 == 0) batt = (const float*)p; else bfcs = (const float*)p;
                c128++; break;
            case 1024: Wfc  = (const float*)p; break;
            case 2048: Wout = (const float*)p; break;
            default: break;   // size-1 scalars ignored
        }
    }

    float* out = (float*)d_out;

    static int smem_set = 0;
    if (!smem_set) {
        cudaFuncSetAttribute(k_fuse3, cudaFuncAttributeMaxDynamicSharedMemorySize,
                             FUSE3_SMEM_BYTES);
        smem_set = 1;
    }

    // Launch order puts k_redmma at position 4 (ncu keyhole captures launch #4).
    k_cvt<<<8, 256>>>(Wred, W1, Watt, Wfc, Wfcs, W2, Wout);

    k_fill_out<<<(out_size + 255) / 256, 256>>>(out, out_size);

    k_map<<<(NPTS + 255) / 256, 256>>>(invp, invo);

    k_redmma<<<NVOX / 64, 128>>>(x, bred, i0, i1, i2, i3);

    {
        long long tot = (long long)4 * NVOX * 8;
        k_scale<<<(unsigned)((tot + 255) / 256), 256>>>(batt);
    }

    k_fuse3<<<NVOX / 64, 128, FUSE3_SMEM_BYTES>>>(bfcs, b2, i0, i1, i2, i3, out);
}